// round 12
// baseline (speedup 1.0000x reference)
#include <cuda_runtime.h>
#include <math.h>

#define NTOT 2048          // B*N
#define KSEL 20

__device__ float  g_part[2 * NTOT * 512]; // K-split partial GEMM results
__device__ float  g_xlxr[NTOT * 512];     // [g][0:256)=xl, [256:512)=xr
__device__ float  g_xrT[4 * 256 * 512];   // [b][d][j] transposed xr

// ---------------- packed f32x2 helpers ----------------
__device__ __forceinline__ double fma2(double a, double b, double c) {
    double d;
    asm("fma.rn.f32x2 %0, %1, %2, %3;" : "=d"(d) : "d"(a), "d"(b), "d"(c));
    return d;
}
__device__ __forceinline__ double add2(double a, double b) {
    double d;
    asm("add.rn.f32x2 %0, %1, %2;" : "=d"(d) : "d"(a), "d"(b));
    return d;
}
__device__ __forceinline__ double abs2(double a) {
    return __longlong_as_double(__double_as_longlong(a) & 0x7fffffff7fffffffULL);
}
__device__ __forceinline__ double dup2(float v) {
    double d;
    asm("mov.b64 %0, {%1, %1};" : "=d"(d) : "f"(v));
    return d;
}
__device__ __forceinline__ float2 unpack2(double a) {
    float2 f;
    asm("mov.b64 {%0, %1}, %2;" : "=f"(f.x), "=f"(f.y) : "d"(a));
    return f;
}

// ---------------------------------------------------------------------------
// Kernel 1: K-split-2 projection GEMM, f32x2 packed over M.
// Tile 128(M) x 64(N), BK=16, 256 threads. Thread: 4 M-pairs x 4 N-cols.
// A [k][m] natural (pairs = adjacent m), B pre-duplicated [k][2n] in smem.
// Inner loop: 16 FFMA2 + 4 LDS.128 per k, zero MOVs. grid (16,8,2).
// ---------------------------------------------------------------------------
__global__ __launch_bounds__(256, 3) void proj_kernel(
    const float* __restrict__ x,
    const float* __restrict__ Wl, const float* __restrict__ bl,
    const float* __restrict__ Wr, const float* __restrict__ br)
{
    __shared__ __align__(16) float As[2][16 * 132];   // [k][m], m=128 (+pad)
    __shared__ __align__(16) float Bs2[2][16 * 136];  // [k][2n] dup'd, n=64
    const int tid = threadIdx.x;
    const int tx = tid & 15;          // N: cols tx*4..tx*4+3
    const int ty = tid >> 4;          // M: rows ty*8..ty*8+7 (4 pairs)
    const int g0 = blockIdx.x * 128;
    const int n0 = blockIdx.y * 64;
    const int kh = blockIdx.z;        // K half
    const float* W    = (n0 < 256) ? Wl : Wr;
    const float* bias = (n0 < 256) ? bl : br;
    const int nw0 = (n0 < 256) ? n0 : n0 - 256;

    const int lmA = tid >> 1;             // 0..127
    const int lkA = (tid & 1) * 8;        // 0 or 8
    const int lmB = tid >> 2;             // 0..63
    const int lkB = (tid & 3) * 4;        // 0,4,8,12

    const float* xp = &x[(g0 + lmA) * 256 + kh * 128 + lkA];
    const float* wp = &W[(nw0 + lmB) * 256 + kh * 128 + lkB];

    double acc[4][4];                     // [m-pair][n-col]
#pragma unroll
    for (int p = 0; p < 4; ++p)
#pragma unroll
        for (int c = 0; c < 4; ++c) acc[p][c] = 0.0;

    float4 a0 = *(const float4*)xp;
    float4 a1 = *(const float4*)(xp + 4);
    float4 bv = *(const float4*)wp;
    {
        float* A = As[0]; float* B = Bs2[0];
        A[(lkA + 0) * 132 + lmA] = a0.x; A[(lkA + 1) * 132 + lmA] = a0.y;
        A[(lkA + 2) * 132 + lmA] = a0.z; A[(lkA + 3) * 132 + lmA] = a0.w;
        A[(lkA + 4) * 132 + lmA] = a1.x; A[(lkA + 5) * 132 + lmA] = a1.y;
        A[(lkA + 6) * 132 + lmA] = a1.z; A[(lkA + 7) * 132 + lmA] = a1.w;
        *(double*)&B[(lkB + 0) * 136 + 2 * lmB] = dup2(bv.x);
        *(double*)&B[(lkB + 1) * 136 + 2 * lmB] = dup2(bv.y);
        *(double*)&B[(lkB + 2) * 136 + 2 * lmB] = dup2(bv.z);
        *(double*)&B[(lkB + 3) * 136 + 2 * lmB] = dup2(bv.w);
    }
    a0 = *(const float4*)(xp + 16);
    a1 = *(const float4*)(xp + 20);
    bv = *(const float4*)(wp + 16);

#pragma unroll 1
    for (int t = 0; t < 8; ++t) {
        __syncthreads();
        if (t < 7) {
            float* A = As[(t + 1) & 1]; float* B = Bs2[(t + 1) & 1];
            A[(lkA + 0) * 132 + lmA] = a0.x; A[(lkA + 1) * 132 + lmA] = a0.y;
            A[(lkA + 2) * 132 + lmA] = a0.z; A[(lkA + 3) * 132 + lmA] = a0.w;
            A[(lkA + 4) * 132 + lmA] = a1.x; A[(lkA + 5) * 132 + lmA] = a1.y;
            A[(lkA + 6) * 132 + lmA] = a1.z; A[(lkA + 7) * 132 + lmA] = a1.w;
            *(double*)&B[(lkB + 0) * 136 + 2 * lmB] = dup2(bv.x);
            *(double*)&B[(lkB + 1) * 136 + 2 * lmB] = dup2(bv.y);
            *(double*)&B[(lkB + 2) * 136 + 2 * lmB] = dup2(bv.z);
            *(double*)&B[(lkB + 3) * 136 + 2 * lmB] = dup2(bv.w);
        }
        if (t < 6) {
            a0 = *(const float4*)(xp + (t + 2) * 16);
            a1 = *(const float4*)(xp + (t + 2) * 16 + 4);
            bv = *(const float4*)(wp + (t + 2) * 16);
        }
        const float* A = As[t & 1]; const float* B = Bs2[t & 1];
#pragma unroll
        for (int k = 0; k < 16; ++k) {
            const double2 a01 = *(const double2*)&A[k * 132 + ty * 8];      // m-pairs 0,1
            const double2 a23 = *(const double2*)&A[k * 132 + ty * 8 + 4];  // m-pairs 2,3
            const double2 b01 = *(const double2*)&B[k * 136 + tx * 8];      // dup cols 0,1
            const double2 b23 = *(const double2*)&B[k * 136 + tx * 8 + 4];  // dup cols 2,3
            acc[0][0] = fma2(a01.x, b01.x, acc[0][0]);
            acc[0][1] = fma2(a01.x, b01.y, acc[0][1]);
            acc[0][2] = fma2(a01.x, b23.x, acc[0][2]);
            acc[0][3] = fma2(a01.x, b23.y, acc[0][3]);
            acc[1][0] = fma2(a01.y, b01.x, acc[1][0]);
            acc[1][1] = fma2(a01.y, b01.y, acc[1][1]);
            acc[1][2] = fma2(a01.y, b23.x, acc[1][2]);
            acc[1][3] = fma2(a01.y, b23.y, acc[1][3]);
            acc[2][0] = fma2(a23.x, b01.x, acc[2][0]);
            acc[2][1] = fma2(a23.x, b01.y, acc[2][1]);
            acc[2][2] = fma2(a23.x, b23.x, acc[2][2]);
            acc[2][3] = fma2(a23.x, b23.y, acc[2][3]);
            acc[3][0] = fma2(a23.y, b01.x, acc[3][0]);
            acc[3][1] = fma2(a23.y, b01.y, acc[3][1]);
            acc[3][2] = fma2(a23.y, b23.x, acc[3][2]);
            acc[3][3] = fma2(a23.y, b23.y, acc[3][3]);
        }
    }

    float* dst = g_part + (size_t)kh * NTOT * 512;
    const float b0 = bias[nw0 + tx * 4 + 0];
    const float b1 = bias[nw0 + tx * 4 + 1];
    const float b2 = bias[nw0 + tx * 4 + 2];
    const float b3 = bias[nw0 + tx * 4 + 3];
#pragma unroll
    for (int p = 0; p < 4; ++p) {
        const float2 c0 = unpack2(acc[p][0]);
        const float2 c1 = unpack2(acc[p][1]);
        const float2 c2 = unpack2(acc[p][2]);
        const float2 c3 = unpack2(acc[p][3]);
        const int row0 = g0 + ty * 8 + 2 * p;
        float4 o0, o1;
        if (kh == 0) {
            o0 = make_float4(c0.x + b0, c1.x + b1, c2.x + b2, c3.x + b3);
            o1 = make_float4(c0.y + b0, c1.y + b1, c2.y + b2, c3.y + b3);
        } else {
            o0 = make_float4(c0.x, c1.x, c2.x, c3.x);
            o1 = make_float4(c0.y, c1.y, c2.y, c3.y);
        }
        *(float4*)&dst[(size_t)row0 * 512 + n0 + tx * 4] = o0;
        *(float4*)&dst[(size_t)(row0 + 1) * 512 + n0 + tx * 4] = o1;
    }
}

// ---------------------------------------------------------------------------
// Kernel 2: sumtrans. Sum 2 K-partials -> g_xlxr; transpose xr -> g_xrT.
// grid 256 (8 g-rows per block). No L/R (moved into pairtop).
// ---------------------------------------------------------------------------
__global__ __launch_bounds__(256) void sumtrans_kernel()
{
    __shared__ __align__(16) float slab[8 * 516];
    const int tid = threadIdx.x;
    const int g0 = blockIdx.x * 8;
    const int b = g0 >> 9;
    const int j0 = g0 & 511;

#pragma unroll
    for (int q = 0; q < 4; ++q) {
        const int f4 = q * 256 + tid;        // 0..1023
        const int row = f4 >> 7, c4 = f4 & 127;
        const size_t ga = (size_t)(g0 + row) * 512 + c4 * 4;
        float4 a = *(const float4*)&g_part[ga];
        const float4 c = *(const float4*)&g_part[(size_t)NTOT * 512 + ga];
        a.x += c.x; a.y += c.y; a.z += c.z; a.w += c.w;
        *(float4*)&g_xlxr[ga] = a;
        *(float4*)&slab[row * 516 + c4 * 4] = a;
    }
    __syncthreads();

    // transpose: thread = d; write 8 consecutive j per d (two float4 stores)
    const int d = tid;
    float v[8];
#pragma unroll
    for (int r = 0; r < 8; ++r) v[r] = slab[r * 516 + 256 + d];
    const size_t o = ((size_t)b * 256 + d) * 512 + j0;
    *(float4*)&g_xrT[o]     = make_float4(v[0], v[1], v[2], v[3]);
    *(float4*)&g_xrT[o + 4] = make_float4(v[4], v[5], v[6], v[7]);
}

// ---------------------------------------------------------------------------
// Kernel 3: FUSED pairwise scores + L/R + top-20 + softmax.
// 256 threads, 8 i-rows/block, grid 256. Thread owns ONE j-pair x 8 rows.
// R_j accumulated in the main loop (ws-weighted, x1.5); L_i per-warp dot.
// ---------------------------------------------------------------------------
__global__ __launch_bounds__(256, 3) void pairtop_kernel(const float* __restrict__ att,
                                                         float* __restrict__ out)
{
    __shared__ double xl2d[256 * 8];   // [d][r] dup'd xl, 16KB
    __shared__ double ws2[256];        // dup'd 0.4*att, 2KB
    __shared__ float  alpha_s[8 * 512];
    __shared__ float  Ls[8];

    const int tid = threadIdx.x;
    const int g0 = blockIdx.x * 8;
    const int b512 = g0 & ~511;
    const int b = b512 >> 9;
    const int w = tid >> 5, l = tid & 31;

    ws2[tid] = dup2(0.4f * att[tid]);
    // L_i: warp w computes 0.6 * dot(att, xl[row w])
    {
        float s = 0.f;
#pragma unroll
        for (int q = 0; q < 8; ++q)
            s += att[l + 32 * q] * g_xlxr[(size_t)(g0 + w) * 512 + l + 32 * q];
#pragma unroll
        for (int off = 16; off; off >>= 1) s += __shfl_xor_sync(0xffffffffu, s, off);
        if (l == 0) Ls[w] = 0.6f * s;
    }
#pragma unroll
    for (int q = 0; q < 8; ++q) {
        const int idx = q * 256 + tid;     // 0..2047
        const int r = idx & 7, d = idx >> 3;
        xl2d[d * 8 + r] = dup2(g_xlxr[(size_t)(g0 + r) * 512 + d]);
    }
    __syncthreads();

    const int jp = tid;                    // j-pair: j = 2jp, 2jp+1
    const double* __restrict__ xrp =
        (const double*)g_xrT + (size_t)b * 256 * 256 + jp;

    double acc[8];
#pragma unroll
    for (int i = 0; i < 8; ++i) acc[i] = 0.0;
    double Racc = 0.0;

    // register double-buffer for xr chunks (4 d each)
    double xr[2][4];
#pragma unroll
    for (int q = 0; q < 4; ++q) xr[0][q] = xrp[(size_t)q * 256];

#pragma unroll 2
    for (int c = 0; c < 64; ++c) {
        const int cur = c & 1, nxt = cur ^ 1;
        if (c < 63) {                       // prefetch next chunk's xr
#pragma unroll
            for (int q = 0; q < 4; ++q)
                xr[nxt][q] = xrp[(size_t)((c + 1) * 4 + q) * 256];
        }
#pragma unroll
        for (int q = 0; q < 4; ++q) {
            const int d = c * 4 + q;
            const double wsd = ws2[d];
            const double2 x01 = *(const double2*)&xl2d[d * 8 + 0];
            const double2 x23 = *(const double2*)&xl2d[d * 8 + 2];
            const double2 x45 = *(const double2*)&xl2d[d * 8 + 4];
            const double2 x67 = *(const double2*)&xl2d[d * 8 + 6];
            const double xv = xr[cur][q];
            Racc   = fma2(wsd, xv, Racc);   // R_j = 1.5 * sum(0.4 att * xr)
            acc[0] = fma2(wsd, abs2(add2(x01.x, xv)), acc[0]);
            acc[1] = fma2(wsd, abs2(add2(x01.y, xv)), acc[1]);
            acc[2] = fma2(wsd, abs2(add2(x23.x, xv)), acc[2]);
            acc[3] = fma2(wsd, abs2(add2(x23.y, xv)), acc[3]);
            acc[4] = fma2(wsd, abs2(add2(x45.x, xv)), acc[4]);
            acc[5] = fma2(wsd, abs2(add2(x45.y, xv)), acc[5]);
            acc[6] = fma2(wsd, abs2(add2(x67.x, xv)), acc[6]);
            acc[7] = fma2(wsd, abs2(add2(x67.y, xv)), acc[7]);
        }
    }
    const float2 rf = unpack2(Racc);
    const float R0 = 1.5f * rf.x, R1 = 1.5f * rf.y;
#pragma unroll
    for (int r = 0; r < 8; ++r) {
        const float2 f = unpack2(acc[r]);
        *(float2*)&alpha_s[r * 512 + 2 * jp] =
            make_float2(Ls[r] + R0 + f.x, Ls[r] + R1 + f.y);
    }
    __syncthreads();

    // ---- top-20 + softmax: warp w handles row w (8 warps, 8 rows) ----
    const float* arow = &alpha_s[w * 512];
    float v[16];
#pragma unroll
    for (int t = 0; t < 16; ++t) v[t] = arow[l + 32 * t];

    float wv = 0.f; int wj = 0;
    for (int kk = 0; kk < KSEL; ++kk) {
        float bv = -INFINITY; int bt = 0;
#pragma unroll
        for (int t = 0; t < 16; ++t)
            if (v[t] > bv) { bv = v[t]; bt = t; }   // strict > keeps lowest j
        int bj = bt * 32 + l;
#pragma unroll
        for (int off = 16; off; off >>= 1) {
            const float ov = __shfl_xor_sync(0xffffffffu, bv, off);
            const int   oj = __shfl_xor_sync(0xffffffffu, bj, off);
            if (ov > bv || (ov == bv && oj < bj)) { bv = ov; bj = oj; }
        }
        if (l == kk) { wv = bv; wj = bj; }
        const int owner = bj & 31, slot = bj >> 5;
        if (l == owner) {
#pragma unroll
            for (int t = 0; t < 16; ++t)
                if (slot == t) v[t] = -INFINITY;
        }
    }

    const float m = __shfl_sync(0xffffffffu, wv, 0);   // largest selected
    const float e = (l < KSEL) ? expf(wv - m) : 0.f;
    float s = e;
#pragma unroll
    for (int off = 16; off; off >>= 1) s += __shfl_xor_sync(0xffffffffu, s, off);
    if (l < KSEL) {
        const int g = g0 + w;
        const int base = g * KSEL + l;
        out[base]                   = (float)g;             // index_i
        out[NTOT * KSEL + base]     = (float)(b512 + wj);   // index_j
        out[2 * NTOT * KSEL + base] = e / s;                // attention
    }
}

// ---------------------------------------------------------------------------
extern "C" void kernel_launch(void* const* d_in, const int* in_sizes, int n_in,
                              void* d_out, int out_size)
{
    const float* x   = (const float*)d_in[0];
    const float* Wl  = (const float*)d_in[3];
    const float* bl  = (const float*)d_in[4];
    const float* Wr  = (const float*)d_in[5];
    const float* br  = (const float*)d_in[6];
    const float* att = (const float*)d_in[7];
    float* out = (float*)d_out;

    proj_kernel<<<dim3(16, 8, 2), 256>>>(x, Wl, bl, Wr, br);
    sumtrans_kernel<<<256, 256>>>();
    pairtop_kernel<<<256, 256>>>(att, out);
}

// round 13
// speedup vs baseline: 1.1043x; 1.1043x over previous
#include <cuda_runtime.h>
#include <math.h>

#define NTOT 2048          // B*N
#define KSEL 20

__device__ float  g_part[2 * NTOT * 512]; // K-split partial GEMM results
__device__ float  g_xlxr[NTOT * 512];     // [g][0:256)=xl, [256:512)=xr
__device__ float  g_xrT[4 * 256 * 512];   // [b][d][j] transposed xr

// ---------------- packed f32x2 helpers ----------------
__device__ __forceinline__ double fma2(double a, double b, double c) {
    double d;
    asm("fma.rn.f32x2 %0, %1, %2, %3;" : "=d"(d) : "d"(a), "d"(b), "d"(c));
    return d;
}
__device__ __forceinline__ double add2(double a, double b) {
    double d;
    asm("add.rn.f32x2 %0, %1, %2;" : "=d"(d) : "d"(a), "d"(b));
    return d;
}
__device__ __forceinline__ double abs2(double a) {
    return __longlong_as_double(__double_as_longlong(a) & 0x7fffffff7fffffffULL);
}
__device__ __forceinline__ double dup2(float v) {
    double d;
    asm("mov.b64 %0, {%1, %1};" : "=d"(d) : "f"(v));
    return d;
}
__device__ __forceinline__ float2 unpack2(double a) {
    float2 f;
    asm("mov.b64 {%0, %1}, %2;" : "=f"(f.x), "=f"(f.y) : "d"(a));
    return f;
}

// ---------------------------------------------------------------------------
// Kernel 1: K-split-2 projection GEMM. Tile 128(M) x 64(N), BK=16, 256 thr.
// Thread: 8 M-rows x 4 N-cols (N packed as 2 f32x2 pairs).
// A stored PRE-DUPLICATED [k][2m] -> inner-loop A reads are broadcast LDS.128
// (zero MOVs); B natural [k][n], double2 read at tx*4 (conflict-free, as R10).
// Inner loop per k: 4 A-LDS(bcast) + 1 B-LDS + 16 FFMA2. grid (16,8,2).
// ---------------------------------------------------------------------------
__global__ __launch_bounds__(256, 3) void proj_kernel(
    const float* __restrict__ x,
    const float* __restrict__ Wl, const float* __restrict__ bl,
    const float* __restrict__ Wr, const float* __restrict__ br)
{
    __shared__ __align__(16) float As2[2][16 * 260];  // [k][2m] dup'd, m=128
    __shared__ __align__(16) float Bs[2][16 * 68];    // [k][n], n=64 (+pad)
    const int tid = threadIdx.x;
    const int tx = tid & 15;          // N: cols tx*4..tx*4+3
    const int ty = tid >> 4;          // M: rows ty*8..ty*8+7
    const int g0 = blockIdx.x * 128;
    const int n0 = blockIdx.y * 64;
    const int kh = blockIdx.z;        // K half
    const float* W    = (n0 < 256) ? Wl : Wr;
    const float* bias = (n0 < 256) ? bl : br;
    const int nw0 = (n0 < 256) ? n0 : n0 - 256;

    const int lmA = tid >> 1;             // 0..127
    const int lkA = (tid & 1) * 8;        // 0 or 8
    const int lmB = tid >> 2;             // 0..63
    const int lkB = (tid & 3) * 4;        // 0,4,8,12

    const float* xp = &x[(g0 + lmA) * 256 + kh * 128 + lkA];
    const float* wp = &W[(nw0 + lmB) * 256 + kh * 128 + lkB];

    double acc[8][2];
#pragma unroll
    for (int i = 0; i < 8; ++i) { acc[i][0] = 0.0; acc[i][1] = 0.0; }

    float4 a0 = *(const float4*)xp;
    float4 a1 = *(const float4*)(xp + 4);
    float4 bv = *(const float4*)wp;
    {
        float* A = As2[0]; float* B = Bs[0];
        *(double*)&A[(lkA + 0) * 260 + 2 * lmA] = dup2(a0.x);
        *(double*)&A[(lkA + 1) * 260 + 2 * lmA] = dup2(a0.y);
        *(double*)&A[(lkA + 2) * 260 + 2 * lmA] = dup2(a0.z);
        *(double*)&A[(lkA + 3) * 260 + 2 * lmA] = dup2(a0.w);
        *(double*)&A[(lkA + 4) * 260 + 2 * lmA] = dup2(a1.x);
        *(double*)&A[(lkA + 5) * 260 + 2 * lmA] = dup2(a1.y);
        *(double*)&A[(lkA + 6) * 260 + 2 * lmA] = dup2(a1.z);
        *(double*)&A[(lkA + 7) * 260 + 2 * lmA] = dup2(a1.w);
        B[(lkB + 0) * 68 + lmB] = bv.x;  B[(lkB + 1) * 68 + lmB] = bv.y;
        B[(lkB + 2) * 68 + lmB] = bv.z;  B[(lkB + 3) * 68 + lmB] = bv.w;
    }
    a0 = *(const float4*)(xp + 16);
    a1 = *(const float4*)(xp + 20);
    bv = *(const float4*)(wp + 16);

#pragma unroll 1
    for (int t = 0; t < 8; ++t) {
        __syncthreads();
        if (t < 7) {
            float* A = As2[(t + 1) & 1]; float* B = Bs[(t + 1) & 1];
            *(double*)&A[(lkA + 0) * 260 + 2 * lmA] = dup2(a0.x);
            *(double*)&A[(lkA + 1) * 260 + 2 * lmA] = dup2(a0.y);
            *(double*)&A[(lkA + 2) * 260 + 2 * lmA] = dup2(a0.z);
            *(double*)&A[(lkA + 3) * 260 + 2 * lmA] = dup2(a0.w);
            *(double*)&A[(lkA + 4) * 260 + 2 * lmA] = dup2(a1.x);
            *(double*)&A[(lkA + 5) * 260 + 2 * lmA] = dup2(a1.y);
            *(double*)&A[(lkA + 6) * 260 + 2 * lmA] = dup2(a1.z);
            *(double*)&A[(lkA + 7) * 260 + 2 * lmA] = dup2(a1.w);
            B[(lkB + 0) * 68 + lmB] = bv.x;  B[(lkB + 1) * 68 + lmB] = bv.y;
            B[(lkB + 2) * 68 + lmB] = bv.z;  B[(lkB + 3) * 68 + lmB] = bv.w;
        }
        if (t < 6) {
            a0 = *(const float4*)(xp + (t + 2) * 16);
            a1 = *(const float4*)(xp + (t + 2) * 16 + 4);
            bv = *(const float4*)(wp + (t + 2) * 16);
        }
        const float* A = As2[t & 1]; const float* B = Bs[t & 1];
#pragma unroll
        for (int k = 0; k < 16; ++k) {
            // rows ty*8+r dup'd at float offset ty*16 + 2r (broadcast: 2 ty/warp)
            const double2 a01 = *(const double2*)&A[k * 260 + ty * 16];
            const double2 a23 = *(const double2*)&A[k * 260 + ty * 16 + 4];
            const double2 a45 = *(const double2*)&A[k * 260 + ty * 16 + 8];
            const double2 a67 = *(const double2*)&A[k * 260 + ty * 16 + 12];
            const double2 b2  = *(const double2*)&B[k * 68 + tx * 4];
            acc[0][0] = fma2(a01.x, b2.x, acc[0][0]);
            acc[0][1] = fma2(a01.x, b2.y, acc[0][1]);
            acc[1][0] = fma2(a01.y, b2.x, acc[1][0]);
            acc[1][1] = fma2(a01.y, b2.y, acc[1][1]);
            acc[2][0] = fma2(a23.x, b2.x, acc[2][0]);
            acc[2][1] = fma2(a23.x, b2.y, acc[2][1]);
            acc[3][0] = fma2(a23.y, b2.x, acc[3][0]);
            acc[3][1] = fma2(a23.y, b2.y, acc[3][1]);
            acc[4][0] = fma2(a45.x, b2.x, acc[4][0]);
            acc[4][1] = fma2(a45.x, b2.y, acc[4][1]);
            acc[5][0] = fma2(a45.y, b2.x, acc[5][0]);
            acc[5][1] = fma2(a45.y, b2.y, acc[5][1]);
            acc[6][0] = fma2(a67.x, b2.x, acc[6][0]);
            acc[6][1] = fma2(a67.x, b2.y, acc[6][1]);
            acc[7][0] = fma2(a67.y, b2.x, acc[7][0]);
            acc[7][1] = fma2(a67.y, b2.y, acc[7][1]);
        }
    }

    float* dst = g_part + (size_t)kh * NTOT * 512;
#pragma unroll
    for (int i = 0; i < 8; ++i) {
        const int row = g0 + ty * 8 + i;
        const float2 p0 = unpack2(acc[i][0]);
        const float2 p1 = unpack2(acc[i][1]);
        float4 o;
        if (kh == 0) {
            o.x = p0.x + bias[nw0 + tx * 4 + 0];
            o.y = p0.y + bias[nw0 + tx * 4 + 1];
            o.z = p1.x + bias[nw0 + tx * 4 + 2];
            o.w = p1.y + bias[nw0 + tx * 4 + 3];
        } else {
            o.x = p0.x; o.y = p0.y; o.z = p1.x; o.w = p1.y;
        }
        *(float4*)&dst[(size_t)row * 512 + n0 + tx * 4] = o;
    }
}

// ---------------------------------------------------------------------------
// Kernel 2: sumtrans. Sum 2 K-partials -> g_xlxr; transpose xr -> g_xrT.
// grid 256 (8 g-rows per block).
// ---------------------------------------------------------------------------
__global__ __launch_bounds__(256) void sumtrans_kernel()
{
    __shared__ __align__(16) float slab[8 * 516];
    const int tid = threadIdx.x;
    const int g0 = blockIdx.x * 8;
    const int b = g0 >> 9;
    const int j0 = g0 & 511;

#pragma unroll
    for (int q = 0; q < 4; ++q) {
        const int f4 = q * 256 + tid;        // 0..1023
        const int row = f4 >> 7, c4 = f4 & 127;
        const size_t ga = (size_t)(g0 + row) * 512 + c4 * 4;
        float4 a = *(const float4*)&g_part[ga];
        const float4 c = *(const float4*)&g_part[(size_t)NTOT * 512 + ga];
        a.x += c.x; a.y += c.y; a.z += c.z; a.w += c.w;
        *(float4*)&g_xlxr[ga] = a;
        *(float4*)&slab[row * 516 + c4 * 4] = a;
    }
    __syncthreads();

    // transpose: thread = d; write 8 consecutive j per d (two float4 stores)
    const int d = tid;
    float v[8];
#pragma unroll
    for (int r = 0; r < 8; ++r) v[r] = slab[r * 516 + 256 + d];
    const size_t o = ((size_t)b * 256 + d) * 512 + j0;
    *(float4*)&g_xrT[o]     = make_float4(v[0], v[1], v[2], v[3]);
    *(float4*)&g_xrT[o + 4] = make_float4(v[4], v[5], v[6], v[7]);
}

// ---------------------------------------------------------------------------
// Kernel 3: FUSED pairwise scores + L/R + top-20 + softmax.
// 256 threads, 8 i-rows/block, grid 256. Thread owns ONE j-pair x 8 rows.
// R_j accumulated in the main loop (ws-weighted, x1.5); L_i per-warp dot.
// ---------------------------------------------------------------------------
__global__ __launch_bounds__(256, 3) void pairtop_kernel(const float* __restrict__ att,
                                                         float* __restrict__ out)
{
    __shared__ double xl2d[256 * 8];   // [d][r] dup'd xl, 16KB
    __shared__ double ws2[256];        // dup'd 0.4*att, 2KB
    __shared__ float  alpha_s[8 * 512];
    __shared__ float  Ls[8];

    const int tid = threadIdx.x;
    const int g0 = blockIdx.x * 8;
    const int b512 = g0 & ~511;
    const int b = b512 >> 9;
    const int w = tid >> 5, l = tid & 31;

    ws2[tid] = dup2(0.4f * att[tid]);
    // L_i: warp w computes 0.6 * dot(att, xl[row w])
    {
        float s = 0.f;
#pragma unroll
        for (int q = 0; q < 8; ++q)
            s += att[l + 32 * q] * g_xlxr[(size_t)(g0 + w) * 512 + l + 32 * q];
#pragma unroll
        for (int off = 16; off; off >>= 1) s += __shfl_xor_sync(0xffffffffu, s, off);
        if (l == 0) Ls[w] = 0.6f * s;
    }
#pragma unroll
    for (int q = 0; q < 8; ++q) {
        const int idx = q * 256 + tid;     // 0..2047
        const int r = idx & 7, d = idx >> 3;
        xl2d[d * 8 + r] = dup2(g_xlxr[(size_t)(g0 + r) * 512 + d]);
    }
    __syncthreads();

    const int jp = tid;                    // j-pair: j = 2jp, 2jp+1
    const double* __restrict__ xrp =
        (const double*)g_xrT + (size_t)b * 256 * 256 + jp;

    double acc[8];
#pragma unroll
    for (int i = 0; i < 8; ++i) acc[i] = 0.0;
    double Racc = 0.0;

    // register double-buffer for xr chunks (4 d each)
    double xr[2][4];
#pragma unroll
    for (int q = 0; q < 4; ++q) xr[0][q] = xrp[(size_t)q * 256];

#pragma unroll 2
    for (int c = 0; c < 64; ++c) {
        const int cur = c & 1, nxt = cur ^ 1;
        if (c < 63) {                       // prefetch next chunk's xr
#pragma unroll
            for (int q = 0; q < 4; ++q)
                xr[nxt][q] = xrp[(size_t)((c + 1) * 4 + q) * 256];
        }
#pragma unroll
        for (int q = 0; q < 4; ++q) {
            const int d = c * 4 + q;
            const double wsd = ws2[d];
            const double2 x01 = *(const double2*)&xl2d[d * 8 + 0];
            const double2 x23 = *(const double2*)&xl2d[d * 8 + 2];
            const double2 x45 = *(const double2*)&xl2d[d * 8 + 4];
            const double2 x67 = *(const double2*)&xl2d[d * 8 + 6];
            const double xv = xr[cur][q];
            Racc   = fma2(wsd, xv, Racc);   // R_j = 1.5 * sum(0.4 att * xr)
            acc[0] = fma2(wsd, abs2(add2(x01.x, xv)), acc[0]);
            acc[1] = fma2(wsd, abs2(add2(x01.y, xv)), acc[1]);
            acc[2] = fma2(wsd, abs2(add2(x23.x, xv)), acc[2]);
            acc[3] = fma2(wsd, abs2(add2(x23.y, xv)), acc[3]);
            acc[4] = fma2(wsd, abs2(add2(x45.x, xv)), acc[4]);
            acc[5] = fma2(wsd, abs2(add2(x45.y, xv)), acc[5]);
            acc[6] = fma2(wsd, abs2(add2(x67.x, xv)), acc[6]);
            acc[7] = fma2(wsd, abs2(add2(x67.y, xv)), acc[7]);
        }
    }
    const float2 rf = unpack2(Racc);
    const float R0 = 1.5f * rf.x, R1 = 1.5f * rf.y;
#pragma unroll
    for (int r = 0; r < 8; ++r) {
        const float2 f = unpack2(acc[r]);
        *(float2*)&alpha_s[r * 512 + 2 * jp] =
            make_float2(Ls[r] + R0 + f.x, Ls[r] + R1 + f.y);
    }
    __syncthreads();

    // ---- top-20 + softmax: warp w handles row w (8 warps, 8 rows) ----
    const float* arow = &alpha_s[w * 512];
    float v[16];
#pragma unroll
    for (int t = 0; t < 16; ++t) v[t] = arow[l + 32 * t];

    float wv = 0.f; int wj = 0;
    for (int kk = 0; kk < KSEL; ++kk) {
        float bv = -INFINITY; int bt = 0;
#pragma unroll
        for (int t = 0; t < 16; ++t)
            if (v[t] > bv) { bv = v[t]; bt = t; }   // strict > keeps lowest j
        int bj = bt * 32 + l;
#pragma unroll
        for (int off = 16; off; off >>= 1) {
            const float ov = __shfl_xor_sync(0xffffffffu, bv, off);
            const int   oj = __shfl_xor_sync(0xffffffffu, bj, off);
            if (ov > bv || (ov == bv && oj < bj)) { bv = ov; bj = oj; }
        }
        if (l == kk) { wv = bv; wj = bj; }
        const int owner = bj & 31, slot = bj >> 5;
        if (l == owner) {
#pragma unroll
            for (int t = 0; t < 16; ++t)
                if (slot == t) v[t] = -INFINITY;
        }
    }

    const float m = __shfl_sync(0xffffffffu, wv, 0);   // largest selected
    const float e = (l < KSEL) ? expf(wv - m) : 0.f;
    float s = e;
#pragma unroll
    for (int off = 16; off; off >>= 1) s += __shfl_xor_sync(0xffffffffu, s, off);
    if (l < KSEL) {
        const int g = g0 + w;
        const int base = g * KSEL + l;
        out[base]                   = (float)g;             // index_i
        out[NTOT * KSEL + base]     = (float)(b512 + wj);   // index_j
        out[2 * NTOT * KSEL + base] = e / s;                // attention
    }
}

// ---------------------------------------------------------------------------
extern "C" void kernel_launch(void* const* d_in, const int* in_sizes, int n_in,
                              void* d_out, int out_size)
{
    const float* x   = (const float*)d_in[0];
    const float* Wl  = (const float*)d_in[3];
    const float* bl  = (const float*)d_in[4];
    const float* Wr  = (const float*)d_in[5];
    const float* br  = (const float*)d_in[6];
    const float* att = (const float*)d_in[7];
    float* out = (float*)d_out;

    proj_kernel<<<dim3(16, 8, 2), 256>>>(x, Wl, bl, Wr, br);
    sumtrans_kernel<<<256, 256>>>();
    pairtop_kernel<<<256, 256>>>(att, out);
}

// round 14
// speedup vs baseline: 1.1545x; 1.0454x over previous
#include <cuda_runtime.h>
#include <math.h>

#define NTOT 2048          // B*N
#define KSEL 20

__device__ float  g_part[2 * NTOT * 512]; // K-split partial GEMM results
__device__ float  g_xlxr[NTOT * 512];     // [g][0:256)=xl, [256:512)=xr
__device__ float  g_xrT[4 * 256 * 512];   // [b][d][j] transposed xr

// ---------------- packed f32x2 helpers ----------------
__device__ __forceinline__ double fma2(double a, double b, double c) {
    double d;
    asm("fma.rn.f32x2 %0, %1, %2, %3;" : "=d"(d) : "d"(a), "d"(b), "d"(c));
    return d;
}
__device__ __forceinline__ double add2(double a, double b) {
    double d;
    asm("add.rn.f32x2 %0, %1, %2;" : "=d"(d) : "d"(a), "d"(b));
    return d;
}
__device__ __forceinline__ double abs2(double a) {
    return __longlong_as_double(__double_as_longlong(a) & 0x7fffffff7fffffffULL);
}
__device__ __forceinline__ double dup2(float v) {
    double d;
    asm("mov.b64 %0, {%1, %1};" : "=d"(d) : "f"(v));
    return d;
}
__device__ __forceinline__ float2 unpack2(double a) {
    float2 f;
    asm("mov.b64 {%0, %1}, %2;" : "=f"(f.x), "=f"(f.y) : "d"(a));
    return f;
}

// ---------------------------------------------------------------------------
// Kernel 1: K-split-2 projection GEMM (R10 version — empirical best).
// Tile 128(M) x 64(N), BK=16, 256 threads, per-thread 8x4, A scalar-broadcast
// + reg-dup, B natural double2. grid (16, 8, 2).
// ---------------------------------------------------------------------------
__global__ __launch_bounds__(256, 3) void proj_kernel(
    const float* __restrict__ x,
    const float* __restrict__ Wl, const float* __restrict__ bl,
    const float* __restrict__ Wr, const float* __restrict__ br)
{
    __shared__ __align__(16) float As[2][16 * 132];  // [k][m], m=128 (+pad)
    __shared__ __align__(16) float Bs[2][16 * 68];   // [k][n], n=64 (+pad)
    const int tid = threadIdx.x;
    const int tx = tid & 15;
    const int ty = tid >> 4;
    const int g0 = blockIdx.x * 128;
    const int n0 = blockIdx.y * 64;
    const int kh = blockIdx.z;
    const float* W    = (n0 < 256) ? Wl : Wr;
    const float* bias = (n0 < 256) ? bl : br;
    const int nw0 = (n0 < 256) ? n0 : n0 - 256;

    const int lmA = tid >> 1;
    const int lkA = (tid & 1) * 8;
    const int lmB = tid >> 2;
    const int lkB = (tid & 3) * 4;

    const float* xp = &x[(g0 + lmA) * 256 + kh * 128 + lkA];
    const float* wp = &W[(nw0 + lmB) * 256 + kh * 128 + lkB];

    double acc[8][2];
#pragma unroll
    for (int i = 0; i < 8; ++i) { acc[i][0] = 0.0; acc[i][1] = 0.0; }

    float4 a0 = *(const float4*)xp;
    float4 a1 = *(const float4*)(xp + 4);
    float4 bv = *(const float4*)wp;
    {
        float* A = As[0]; float* B = Bs[0];
        A[(lkA + 0) * 132 + lmA] = a0.x; A[(lkA + 1) * 132 + lmA] = a0.y;
        A[(lkA + 2) * 132 + lmA] = a0.z; A[(lkA + 3) * 132 + lmA] = a0.w;
        A[(lkA + 4) * 132 + lmA] = a1.x; A[(lkA + 5) * 132 + lmA] = a1.y;
        A[(lkA + 6) * 132 + lmA] = a1.z; A[(lkA + 7) * 132 + lmA] = a1.w;
        B[(lkB + 0) * 68 + lmB] = bv.x;  B[(lkB + 1) * 68 + lmB] = bv.y;
        B[(lkB + 2) * 68 + lmB] = bv.z;  B[(lkB + 3) * 68 + lmB] = bv.w;
    }
    a0 = *(const float4*)(xp + 16);
    a1 = *(const float4*)(xp + 20);
    bv = *(const float4*)(wp + 16);

#pragma unroll 1
    for (int t = 0; t < 8; ++t) {
        __syncthreads();
        if (t < 7) {
            float* A = As[(t + 1) & 1]; float* B = Bs[(t + 1) & 1];
            A[(lkA + 0) * 132 + lmA] = a0.x; A[(lkA + 1) * 132 + lmA] = a0.y;
            A[(lkA + 2) * 132 + lmA] = a0.z; A[(lkA + 3) * 132 + lmA] = a0.w;
            A[(lkA + 4) * 132 + lmA] = a1.x; A[(lkA + 5) * 132 + lmA] = a1.y;
            A[(lkA + 6) * 132 + lmA] = a1.z; A[(lkA + 7) * 132 + lmA] = a1.w;
            B[(lkB + 0) * 68 + lmB] = bv.x;  B[(lkB + 1) * 68 + lmB] = bv.y;
            B[(lkB + 2) * 68 + lmB] = bv.z;  B[(lkB + 3) * 68 + lmB] = bv.w;
        }
        if (t < 6) {
            a0 = *(const float4*)(xp + (t + 2) * 16);
            a1 = *(const float4*)(xp + (t + 2) * 16 + 4);
            bv = *(const float4*)(wp + (t + 2) * 16);
        }
        const float* A = As[t & 1]; const float* B = Bs[t & 1];
#pragma unroll
        for (int k = 0; k < 16; ++k) {
            const float4 r0 = *(const float4*)&A[k * 132 + ty * 8];
            const float4 r1 = *(const float4*)&A[k * 132 + ty * 8 + 4];
            const double2 b2 = *(const double2*)&B[k * 68 + tx * 4];
            double d;
            d = dup2(r0.x); acc[0][0] = fma2(d, b2.x, acc[0][0]);
                            acc[0][1] = fma2(d, b2.y, acc[0][1]);
            d = dup2(r0.y); acc[1][0] = fma2(d, b2.x, acc[1][0]);
                            acc[1][1] = fma2(d, b2.y, acc[1][1]);
            d = dup2(r0.z); acc[2][0] = fma2(d, b2.x, acc[2][0]);
                            acc[2][1] = fma2(d, b2.y, acc[2][1]);
            d = dup2(r0.w); acc[3][0] = fma2(d, b2.x, acc[3][0]);
                            acc[3][1] = fma2(d, b2.y, acc[3][1]);
            d = dup2(r1.x); acc[4][0] = fma2(d, b2.x, acc[4][0]);
                            acc[4][1] = fma2(d, b2.y, acc[4][1]);
            d = dup2(r1.y); acc[5][0] = fma2(d, b2.x, acc[5][0]);
                            acc[5][1] = fma2(d, b2.y, acc[5][1]);
            d = dup2(r1.z); acc[6][0] = fma2(d, b2.x, acc[6][0]);
                            acc[6][1] = fma2(d, b2.y, acc[6][1]);
            d = dup2(r1.w); acc[7][0] = fma2(d, b2.x, acc[7][0]);
                            acc[7][1] = fma2(d, b2.y, acc[7][1]);
        }
    }

    float* dst = g_part + (size_t)kh * NTOT * 512;
#pragma unroll
    for (int i = 0; i < 8; ++i) {
        const int row = g0 + ty * 8 + i;
        const float2 p0 = unpack2(acc[i][0]);
        const float2 p1 = unpack2(acc[i][1]);
        float4 o;
        if (kh == 0) {
            o.x = p0.x + bias[nw0 + tx * 4 + 0];
            o.y = p0.y + bias[nw0 + tx * 4 + 1];
            o.z = p1.x + bias[nw0 + tx * 4 + 2];
            o.w = p1.y + bias[nw0 + tx * 4 + 3];
        } else {
            o.x = p0.x; o.y = p0.y; o.z = p1.x; o.w = p1.y;
        }
        *(float4*)&dst[(size_t)row * 512 + n0 + tx * 4] = o;
    }
}

// ---------------------------------------------------------------------------
// Kernel 2: sumtrans. Sum 2 K-partials -> g_xlxr; transpose xr -> g_xrT.
// grid 256 (8 g-rows per block).
// ---------------------------------------------------------------------------
__global__ __launch_bounds__(256) void sumtrans_kernel()
{
    __shared__ __align__(16) float slab[8 * 516];
    const int tid = threadIdx.x;
    const int g0 = blockIdx.x * 8;
    const int b = g0 >> 9;
    const int j0 = g0 & 511;

#pragma unroll
    for (int q = 0; q < 4; ++q) {
        const int f4 = q * 256 + tid;
        const int row = f4 >> 7, c4 = f4 & 127;
        const size_t ga = (size_t)(g0 + row) * 512 + c4 * 4;
        float4 a = *(const float4*)&g_part[ga];
        const float4 c = *(const float4*)&g_part[(size_t)NTOT * 512 + ga];
        a.x += c.x; a.y += c.y; a.z += c.z; a.w += c.w;
        *(float4*)&g_xlxr[ga] = a;
        *(float4*)&slab[row * 516 + c4 * 4] = a;
    }
    __syncthreads();

    const int d = tid;
    float v[8];
#pragma unroll
    for (int r = 0; r < 8; ++r) v[r] = slab[r * 516 + 256 + d];
    const size_t o = ((size_t)b * 256 + d) * 512 + j0;
    *(float4*)&g_xrT[o]     = make_float4(v[0], v[1], v[2], v[3]);
    *(float4*)&g_xrT[o + 4] = make_float4(v[4], v[5], v[6], v[7]);
}

// ---------------------------------------------------------------------------
// Kernel 3: FUSED pairwise + L/R + top-20 + softmax, IN-BLOCK D-SPLIT.
// 512 threads: half h = tid>>8 accumulates d in [h*128, h*128+128).
// Thread owns ONE j-pair (tid&255) x 8 rows. 16 warps/block -> 4/SMSP.
// Partials combined in smem; topk by threads 0..255 (warp w <-> row w).
// ---------------------------------------------------------------------------
__global__ void pairtop_kernel(const float* __restrict__ att,
                               float* __restrict__ out)
{
    __shared__ double xl2d[256 * 8];   // [d][r] dup'd xl, 16KB
    __shared__ double ws2[256];        // dup'd 0.4*att, 2KB
    __shared__ float  alpha_s[8 * 512];// 16KB
    __shared__ double Rs0[256];        // half-0 partial R (packed), 2KB
    __shared__ float  Ls[8];

    const int tid = threadIdx.x;
    const int g0 = blockIdx.x * 8;
    const int b512 = g0 & ~511;
    const int b = b512 >> 9;
    const int w = tid >> 5, l = tid & 31;
    const int half = tid >> 8;            // 0 or 1
    const int jp = tid & 255;             // j-pair: j = 2jp, 2jp+1

    if (half == 0) ws2[tid] = dup2(0.4f * att[tid]);
    // L_i: warp w (<8) computes 0.6 * dot(att, xl[row w])
    if (w < 8) {
        float s = 0.f;
#pragma unroll
        for (int q = 0; q < 8; ++q)
            s += att[l + 32 * q] * g_xlxr[(size_t)(g0 + w) * 512 + l + 32 * q];
#pragma unroll
        for (int off = 16; off; off >>= 1) s += __shfl_xor_sync(0xffffffffu, s, off);
        if (l == 0) Ls[w] = 0.6f * s;
    }
#pragma unroll
    for (int q = 0; q < 4; ++q) {
        const int idx = q * 512 + tid;     // 0..2047
        const int r = idx & 7, d = idx >> 3;
        xl2d[d * 8 + r] = dup2(g_xlxr[(size_t)(g0 + r) * 512 + d]);
    }
    __syncthreads();

    const int d0 = half * 128;             // this half's d range start
    const double* __restrict__ xrp =
        (const double*)g_xrT + ((size_t)b * 256 + d0) * 256 + jp;

    double acc[8];
#pragma unroll
    for (int i = 0; i < 8; ++i) acc[i] = 0.0;
    double Racc = 0.0;

    // register double-buffer for xr chunks (4 d each), 32 chunks per half
    double xr[2][4];
#pragma unroll
    for (int q = 0; q < 4; ++q) xr[0][q] = xrp[(size_t)q * 256];

#pragma unroll 2
    for (int c = 0; c < 32; ++c) {
        const int cur = c & 1, nxt = cur ^ 1;
        if (c < 31) {
#pragma unroll
            for (int q = 0; q < 4; ++q)
                xr[nxt][q] = xrp[(size_t)((c + 1) * 4 + q) * 256];
        }
#pragma unroll
        for (int q = 0; q < 4; ++q) {
            const int d = d0 + c * 4 + q;
            const double wsd = ws2[d];
            const double2 x01 = *(const double2*)&xl2d[d * 8 + 0];
            const double2 x23 = *(const double2*)&xl2d[d * 8 + 2];
            const double2 x45 = *(const double2*)&xl2d[d * 8 + 4];
            const double2 x67 = *(const double2*)&xl2d[d * 8 + 6];
            const double xv = xr[cur][q];
            Racc   = fma2(wsd, xv, Racc);
            acc[0] = fma2(wsd, abs2(add2(x01.x, xv)), acc[0]);
            acc[1] = fma2(wsd, abs2(add2(x01.y, xv)), acc[1]);
            acc[2] = fma2(wsd, abs2(add2(x23.x, xv)), acc[2]);
            acc[3] = fma2(wsd, abs2(add2(x23.y, xv)), acc[3]);
            acc[4] = fma2(wsd, abs2(add2(x45.x, xv)), acc[4]);
            acc[5] = fma2(wsd, abs2(add2(x45.y, xv)), acc[5]);
            acc[6] = fma2(wsd, abs2(add2(x67.x, xv)), acc[6]);
            acc[7] = fma2(wsd, abs2(add2(x67.y, xv)), acc[7]);
        }
    }

    if (half == 0) {                       // half 0: raw partials to smem
        Rs0[jp] = Racc;
#pragma unroll
        for (int r = 0; r < 8; ++r) {
            const float2 f = unpack2(acc[r]);
            *(float2*)&alpha_s[r * 512 + 2 * jp] = make_float2(f.x, f.y);
        }
    }
    __syncthreads();
    if (half == 1) {                       // half 1: combine + L + R
        const float2 ra = unpack2(Rs0[jp]);
        const float2 rb = unpack2(Racc);
        const float R0 = 1.5f * (ra.x + rb.x);
        const float R1 = 1.5f * (ra.y + rb.y);
#pragma unroll
        for (int r = 0; r < 8; ++r) {
            const float2 f = unpack2(acc[r]);
            float2 p = *(const float2*)&alpha_s[r * 512 + 2 * jp];
            p.x = Ls[r] + R0 + (p.x + f.x);
            p.y = Ls[r] + R1 + (p.y + f.y);
            *(float2*)&alpha_s[r * 512 + 2 * jp] = p;
        }
    }
    __syncthreads();

    // ---- top-20 + softmax: threads 0..255, warp w handles row w ----
    if (half == 0) {
        const float* arow = &alpha_s[w * 512];
        float v[16];
#pragma unroll
        for (int t = 0; t < 16; ++t) v[t] = arow[l + 32 * t];

        float wv = 0.f; int wj = 0;
        for (int kk = 0; kk < KSEL; ++kk) {
            float bv = -INFINITY; int bt = 0;
#pragma unroll
            for (int t = 0; t < 16; ++t)
                if (v[t] > bv) { bv = v[t]; bt = t; }   // strict > keeps lowest j
            int bj = bt * 32 + l;
#pragma unroll
            for (int off = 16; off; off >>= 1) {
                const float ov = __shfl_xor_sync(0xffffffffu, bv, off);
                const int   oj = __shfl_xor_sync(0xffffffffu, bj, off);
                if (ov > bv || (ov == bv && oj < bj)) { bv = ov; bj = oj; }
            }
            if (l == kk) { wv = bv; wj = bj; }
            const int owner = bj & 31, slot = bj >> 5;
            if (l == owner) {
#pragma unroll
                for (int t = 0; t < 16; ++t)
                    if (slot == t) v[t] = -INFINITY;
            }
        }

        const float m = __shfl_sync(0xffffffffu, wv, 0);
        const float e = (l < KSEL) ? expf(wv - m) : 0.f;
        float s = e;
#pragma unroll
        for (int off = 16; off; off >>= 1) s += __shfl_xor_sync(0xffffffffu, s, off);
        if (l < KSEL) {
            const int g = g0 + w;
            const int base = g * KSEL + l;
            out[base]                   = (float)g;             // index_i
            out[NTOT * KSEL + base]     = (float)(b512 + wj);   // index_j
            out[2 * NTOT * KSEL + base] = e / s;                // attention
        }
    }
}

// ---------------------------------------------------------------------------
extern "C" void kernel_launch(void* const* d_in, const int* in_sizes, int n_in,
                              void* d_out, int out_size)
{
    const float* x   = (const float*)d_in[0];
    const float* Wl  = (const float*)d_in[3];
    const float* bl  = (const float*)d_in[4];
    const float* Wr  = (const float*)d_in[5];
    const float* br  = (const float*)d_in[6];
    const float* att = (const float*)d_in[7];
    float* out = (float*)d_out;

    proj_kernel<<<dim3(16, 8, 2), 256>>>(x, Wl, bl, Wr, br);
    sumtrans_kernel<<<256, 256>>>();
    pairtop_kernel<<<256, 512>>>(att, out);
}

// round 15
// speedup vs baseline: 1.1930x; 1.0334x over previous
#include <cuda_runtime.h>
#include <math.h>

#define NTOT 2048          // B*N
#define KSEL 20

__device__ float  g_xlxr[NTOT * 512];     // [g][0:256)=xl (xr half unused)
__device__ float  g_xrT[4 * 256 * 512];   // [b][d][j] transposed xr

// ---------------- packed f32x2 helpers ----------------
__device__ __forceinline__ double fma2(double a, double b, double c) {
    double d;
    asm("fma.rn.f32x2 %0, %1, %2, %3;" : "=d"(d) : "d"(a), "d"(b), "d"(c));
    return d;
}
__device__ __forceinline__ double add2(double a, double b) {
    double d;
    asm("add.rn.f32x2 %0, %1, %2;" : "=d"(d) : "d"(a), "d"(b));
    return d;
}
__device__ __forceinline__ double abs2(double a) {
    return __longlong_as_double(__double_as_longlong(a) & 0x7fffffff7fffffffULL);
}
__device__ __forceinline__ double dup2(float v) {
    double d;
    asm("mov.b64 %0, {%1, %1};" : "=d"(d) : "f"(v));
    return d;
}
__device__ __forceinline__ float2 unpack2(double a) {
    float2 f;
    asm("mov.b64 {%0, %1}, %2;" : "=f"(f.x), "=f"(f.y) : "d"(a));
    return f;
}

// ---------------------------------------------------------------------------
// Kernel 1: FULL-K projection GEMM + fused output routing.
// Tile 128(M) x 64(N), BK=16 x 16 tiles, 256 threads, per-thread 8x4
// (R10 inner loop: A scalar-broadcast + reg-dup, B natural double2).
// grid (16, 8). xl blocks (n0<256) -> g_xlxr; xr blocks -> in-block
// transpose -> g_xrT (smem pool unions GEMM buffers with T[64][132]).
// ---------------------------------------------------------------------------
#define AS_OFF(s) ((s) * 2112)            // 16*132
#define BS_OFF(s) (4224 + (s) * 1088)     // 16*68

__global__ __launch_bounds__(256, 3) void proj_kernel(
    const float* __restrict__ x,
    const float* __restrict__ Wl, const float* __restrict__ bl,
    const float* __restrict__ Wr, const float* __restrict__ br)
{
    __shared__ __align__(16) float pool[8448];   // max(6400 gemm, 8448 T)
    const int tid = threadIdx.x;
    const int tx = tid & 15;
    const int ty = tid >> 4;
    const int g0 = blockIdx.x * 128;
    const int n0 = blockIdx.y * 64;
    const float* W    = (n0 < 256) ? Wl : Wr;
    const float* bias = (n0 < 256) ? bl : br;
    const int nw0 = (n0 < 256) ? n0 : n0 - 256;

    const int lmA = tid >> 1;
    const int lkA = (tid & 1) * 8;
    const int lmB = tid >> 2;
    const int lkB = (tid & 3) * 4;

    const float* xp = &x[(g0 + lmA) * 256 + lkA];
    const float* wp = &W[(nw0 + lmB) * 256 + lkB];

    double acc[8][2];
#pragma unroll
    for (int i = 0; i < 8; ++i) { acc[i][0] = 0.0; acc[i][1] = 0.0; }

    float4 a0 = *(const float4*)xp;
    float4 a1 = *(const float4*)(xp + 4);
    float4 bv = *(const float4*)wp;
    {
        float* A = pool + AS_OFF(0); float* B = pool + BS_OFF(0);
        A[(lkA + 0) * 132 + lmA] = a0.x; A[(lkA + 1) * 132 + lmA] = a0.y;
        A[(lkA + 2) * 132 + lmA] = a0.z; A[(lkA + 3) * 132 + lmA] = a0.w;
        A[(lkA + 4) * 132 + lmA] = a1.x; A[(lkA + 5) * 132 + lmA] = a1.y;
        A[(lkA + 6) * 132 + lmA] = a1.z; A[(lkA + 7) * 132 + lmA] = a1.w;
        B[(lkB + 0) * 68 + lmB] = bv.x;  B[(lkB + 1) * 68 + lmB] = bv.y;
        B[(lkB + 2) * 68 + lmB] = bv.z;  B[(lkB + 3) * 68 + lmB] = bv.w;
    }
    a0 = *(const float4*)(xp + 16);
    a1 = *(const float4*)(xp + 20);
    bv = *(const float4*)(wp + 16);

#pragma unroll 1
    for (int t = 0; t < 16; ++t) {
        __syncthreads();
        if (t < 15) {
            float* A = pool + AS_OFF((t + 1) & 1); float* B = pool + BS_OFF((t + 1) & 1);
            A[(lkA + 0) * 132 + lmA] = a0.x; A[(lkA + 1) * 132 + lmA] = a0.y;
            A[(lkA + 2) * 132 + lmA] = a0.z; A[(lkA + 3) * 132 + lmA] = a0.w;
            A[(lkA + 4) * 132 + lmA] = a1.x; A[(lkA + 5) * 132 + lmA] = a1.y;
            A[(lkA + 6) * 132 + lmA] = a1.z; A[(lkA + 7) * 132 + lmA] = a1.w;
            B[(lkB + 0) * 68 + lmB] = bv.x;  B[(lkB + 1) * 68 + lmB] = bv.y;
            B[(lkB + 2) * 68 + lmB] = bv.z;  B[(lkB + 3) * 68 + lmB] = bv.w;
        }
        if (t < 14) {
            a0 = *(const float4*)(xp + (t + 2) * 16);
            a1 = *(const float4*)(xp + (t + 2) * 16 + 4);
            bv = *(const float4*)(wp + (t + 2) * 16);
        }
        const float* A = pool + AS_OFF(t & 1); const float* B = pool + BS_OFF(t & 1);
#pragma unroll
        for (int k = 0; k < 16; ++k) {
            const float4 r0 = *(const float4*)&A[k * 132 + ty * 8];
            const float4 r1 = *(const float4*)&A[k * 132 + ty * 8 + 4];
            const double2 b2 = *(const double2*)&B[k * 68 + tx * 4];
            double d;
            d = dup2(r0.x); acc[0][0] = fma2(d, b2.x, acc[0][0]);
                            acc[0][1] = fma2(d, b2.y, acc[0][1]);
            d = dup2(r0.y); acc[1][0] = fma2(d, b2.x, acc[1][0]);
                            acc[1][1] = fma2(d, b2.y, acc[1][1]);
            d = dup2(r0.z); acc[2][0] = fma2(d, b2.x, acc[2][0]);
                            acc[2][1] = fma2(d, b2.y, acc[2][1]);
            d = dup2(r0.w); acc[3][0] = fma2(d, b2.x, acc[3][0]);
                            acc[3][1] = fma2(d, b2.y, acc[3][1]);
            d = dup2(r1.x); acc[4][0] = fma2(d, b2.x, acc[4][0]);
                            acc[4][1] = fma2(d, b2.y, acc[4][1]);
            d = dup2(r1.y); acc[5][0] = fma2(d, b2.x, acc[5][0]);
                            acc[5][1] = fma2(d, b2.y, acc[5][1]);
            d = dup2(r1.z); acc[6][0] = fma2(d, b2.x, acc[6][0]);
                            acc[6][1] = fma2(d, b2.y, acc[6][1]);
            d = dup2(r1.w); acc[7][0] = fma2(d, b2.x, acc[7][0]);
                            acc[7][1] = fma2(d, b2.y, acc[7][1]);
        }
    }

    const float b0 = bias[nw0 + tx * 4 + 0];
    const float b1 = bias[nw0 + tx * 4 + 1];
    const float b2f = bias[nw0 + tx * 4 + 2];
    const float b3 = bias[nw0 + tx * 4 + 3];

    if (n0 < 256) {
        // xl half: direct final write to g_xlxr
#pragma unroll
        for (int i = 0; i < 8; ++i) {
            const int row = g0 + ty * 8 + i;
            const float2 p0 = unpack2(acc[i][0]);
            const float2 p1 = unpack2(acc[i][1]);
            *(float4*)&g_xlxr[(size_t)row * 512 + n0 + tx * 4] =
                make_float4(p0.x + b0, p0.y + b1, p1.x + b2f, p1.y + b3);
        }
    } else {
        // xr half: transpose in smem -> g_xrT[b][d][j]
        const int d0 = n0 - 256;
        const int b = g0 >> 9;
        const int j0 = g0 & 511;
        __syncthreads();                  // main-loop smem reads all done
        float* T = pool;                  // [64 d][132 j-stride]
#pragma unroll
        for (int c = 0; c < 4; ++c) {
            float r[8];
#pragma unroll
            for (int i = 0; i < 8; ++i) {
                const float2 p = unpack2(acc[i][c >> 1]);
                r[i] = ((c & 1) ? p.y : p.x) + ((c == 0) ? b0 : (c == 1) ? b1
                                              : (c == 2) ? b2f : b3);
            }
            float* dst = &T[(tx * 4 + c) * 132 + ty * 8];
            *(float4*)dst       = make_float4(r[0], r[1], r[2], r[3]);
            *(float4*)(dst + 4) = make_float4(r[4], r[5], r[6], r[7]);
        }
        __syncthreads();
#pragma unroll
        for (int p = 0; p < 8; ++p) {
            const int idx = p * 256 + tid;    // 0..2047 float4 ids
            const int dl = idx >> 5, c4 = idx & 31;
            *(float4*)&g_xrT[((size_t)b * 256 + d0 + dl) * 512 + j0 + c4 * 4] =
                *(const float4*)&T[dl * 132 + c4 * 4];
        }
    }
}

// ---------------------------------------------------------------------------
// Kernel 2: FUSED pairwise + L/R + top-20 + softmax, IN-BLOCK D-SPLIT (R14).
// 512 threads: half h = tid>>8 accumulates d in [h*128, h*128+128).
// Thread owns ONE j-pair (tid&255) x 8 rows. Partials combined in smem;
// topk by threads 0..255 (warp w <-> row w).
// ---------------------------------------------------------------------------
__global__ void pairtop_kernel(const float* __restrict__ att,
                               float* __restrict__ out)
{
    __shared__ double xl2d[256 * 8];   // [d][r] dup'd xl, 16KB
    __shared__ double ws2[256];        // dup'd 0.4*att, 2KB
    __shared__ float  alpha_s[8 * 512];// 16KB
    __shared__ double Rs0[256];        // half-0 partial R (packed), 2KB
    __shared__ float  Ls[8];

    const int tid = threadIdx.x;
    const int g0 = blockIdx.x * 8;
    const int b512 = g0 & ~511;
    const int b = b512 >> 9;
    const int w = tid >> 5, l = tid & 31;
    const int half = tid >> 8;            // 0 or 1
    const int jp = tid & 255;             // j-pair: j = 2jp, 2jp+1

    if (half == 0) ws2[tid] = dup2(0.4f * att[tid]);
    // L_i: warp w (<8) computes 0.6 * dot(att, xl[row w])
    if (w < 8) {
        float s = 0.f;
#pragma unroll
        for (int q = 0; q < 8; ++q)
            s += att[l + 32 * q] * g_xlxr[(size_t)(g0 + w) * 512 + l + 32 * q];
#pragma unroll
        for (int off = 16; off; off >>= 1) s += __shfl_xor_sync(0xffffffffu, s, off);
        if (l == 0) Ls[w] = 0.6f * s;
    }
#pragma unroll
    for (int q = 0; q < 4; ++q) {
        const int idx = q * 512 + tid;     // 0..2047
        const int r = idx & 7, d = idx >> 3;
        xl2d[d * 8 + r] = dup2(g_xlxr[(size_t)(g0 + r) * 512 + d]);
    }
    __syncthreads();

    const int d0 = half * 128;
    const double* __restrict__ xrp =
        (const double*)g_xrT + ((size_t)b * 256 + d0) * 256 + jp;

    double acc[8];
#pragma unroll
    for (int i = 0; i < 8; ++i) acc[i] = 0.0;
    double Racc = 0.0;

    double xr[2][4];
#pragma unroll
    for (int q = 0; q < 4; ++q) xr[0][q] = xrp[(size_t)q * 256];

#pragma unroll 2
    for (int c = 0; c < 32; ++c) {
        const int cur = c & 1, nxt = cur ^ 1;
        if (c < 31) {
#pragma unroll
            for (int q = 0; q < 4; ++q)
                xr[nxt][q] = xrp[(size_t)((c + 1) * 4 + q) * 256];
        }
#pragma unroll
        for (int q = 0; q < 4; ++q) {
            const int d = d0 + c * 4 + q;
            const double wsd = ws2[d];
            const double2 x01 = *(const double2*)&xl2d[d * 8 + 0];
            const double2 x23 = *(const double2*)&xl2d[d * 8 + 2];
            const double2 x45 = *(const double2*)&xl2d[d * 8 + 4];
            const double2 x67 = *(const double2*)&xl2d[d * 8 + 6];
            const double xv = xr[cur][q];
            Racc   = fma2(wsd, xv, Racc);
            acc[0] = fma2(wsd, abs2(add2(x01.x, xv)), acc[0]);
            acc[1] = fma2(wsd, abs2(add2(x01.y, xv)), acc[1]);
            acc[2] = fma2(wsd, abs2(add2(x23.x, xv)), acc[2]);
            acc[3] = fma2(wsd, abs2(add2(x23.y, xv)), acc[3]);
            acc[4] = fma2(wsd, abs2(add2(x45.x, xv)), acc[4]);
            acc[5] = fma2(wsd, abs2(add2(x45.y, xv)), acc[5]);
            acc[6] = fma2(wsd, abs2(add2(x67.x, xv)), acc[6]);
            acc[7] = fma2(wsd, abs2(add2(x67.y, xv)), acc[7]);
        }
    }

    if (half == 0) {
        Rs0[jp] = Racc;
#pragma unroll
        for (int r = 0; r < 8; ++r) {
            const float2 f = unpack2(acc[r]);
            *(float2*)&alpha_s[r * 512 + 2 * jp] = make_float2(f.x, f.y);
        }
    }
    __syncthreads();
    if (half == 1) {
        const float2 ra = unpack2(Rs0[jp]);
        const float2 rb = unpack2(Racc);
        const float R0 = 1.5f * (ra.x + rb.x);
        const float R1 = 1.5f * (ra.y + rb.y);
#pragma unroll
        for (int r = 0; r < 8; ++r) {
            const float2 f = unpack2(acc[r]);
            float2 p = *(const float2*)&alpha_s[r * 512 + 2 * jp];
            p.x = Ls[r] + R0 + (p.x + f.x);
            p.y = Ls[r] + R1 + (p.y + f.y);
            *(float2*)&alpha_s[r * 512 + 2 * jp] = p;
        }
    }
    __syncthreads();

    // ---- top-20 + softmax: threads 0..255, warp w handles row w ----
    if (half == 0) {
        const float* arow = &alpha_s[w * 512];
        float v[16];
#pragma unroll
        for (int t = 0; t < 16; ++t) v[t] = arow[l + 32 * t];

        float wv = 0.f; int wj = 0;
        for (int kk = 0; kk < KSEL; ++kk) {
            float bv = -INFINITY; int bt = 0;
#pragma unroll
            for (int t = 0; t < 16; ++t)
                if (v[t] > bv) { bv = v[t]; bt = t; }   // strict > keeps lowest j
            int bj = bt * 32 + l;
#pragma unroll
            for (int off = 16; off; off >>= 1) {
                const float ov = __shfl_xor_sync(0xffffffffu, bv, off);
                const int   oj = __shfl_xor_sync(0xffffffffu, bj, off);
                if (ov > bv || (ov == bv && oj < bj)) { bv = ov; bj = oj; }
            }
            if (l == kk) { wv = bv; wj = bj; }
            const int owner = bj & 31, slot = bj >> 5;
            if (l == owner) {
#pragma unroll
                for (int t = 0; t < 16; ++t)
                    if (slot == t) v[t] = -INFINITY;
            }
        }

        const float m = __shfl_sync(0xffffffffu, wv, 0);
        const float e = (l < KSEL) ? expf(wv - m) : 0.f;
        float s = e;
#pragma unroll
        for (int off = 16; off; off >>= 1) s += __shfl_xor_sync(0xffffffffu, s, off);
        if (l < KSEL) {
            const int g = g0 + w;
            const int base = g * KSEL + l;
            out[base]                   = (float)g;             // index_i
            out[NTOT * KSEL + base]     = (float)(b512 + wj);   // index_j
            out[2 * NTOT * KSEL + base] = e / s;                // attention
        }
    }
}

// ---------------------------------------------------------------------------
extern "C" void kernel_launch(void* const* d_in, const int* in_sizes, int n_in,
                              void* d_out, int out_size)
{
    const float* x   = (const float*)d_in[0];
    const float* Wl  = (const float*)d_in[3];
    const float* bl  = (const float*)d_in[4];
    const float* Wr  = (const float*)d_in[5];
    const float* br  = (const float*)d_in[6];
    const float* att = (const float*)d_in[7];
    float* out = (float*)d_out;

    proj_kernel<<<dim3(16, 8), 256>>>(x, Wl, bl, Wr, br);
    pairtop_kernel<<<256, 512>>>(att, out);
}